// round 17
// baseline (speedup 1.0000x reference)
#include <cuda_runtime.h>
#include <cuda_fp16.h>
#include <mma.h>
#include <math.h>
#include <stdint.h>

using namespace nvcuda;

#define BB   32
#define LL   4096
#define PP   16
#define SS   257
#define DD   512
#define HH   8
#define DHD  64
#define NLAY 8
#define FFD  2048
#define NCLS 4
#define TT   (BB*SS)      /* 8224 */
#define TPAD 8320         /* 65*128 */
#define KCONV 8192
#define MCONV 8192
#define NQKV 1536
#define KVPARTS 4
#define SPART 72

// ---------------- scratch (device globals; no allocations) ----------------
__device__ float  g_x[TPAD*DD];
__device__ __half g_xh[TPAD*DD];
__device__ __half g_qkvh[(size_t)TPAD*NQKV];
__device__ __half g_attn[TPAD*DD];
__device__ __half g_h[(size_t)TPAD*FFD];
__device__ float  g_kvp[KVPARTS][BB*HH*DHD*DHD];
__device__ float  g_ksump[KVPARTS][BB*HH*DHD];
__device__ float  g_len[BB];
__device__ float  g_cs[SS*32*2];
// fp16 weights, native [K][N] layout except conv ([N][K])
__device__ __half g_Wc[(size_t)DD*KCONV];
__device__ __half g_embt[(size_t)32000*DD];
__device__ __half g_Wqkv[(size_t)NLAY*DD*NQKV];
__device__ float  g_bqkv[NLAY*NQKV];
__device__ __half g_Woh[(size_t)NLAY*DD*DD];
__device__ __half g_W1h[(size_t)NLAY*DD*FFD];
__device__ __half g_W2h[(size_t)NLAY*FFD*DD];

// ---------------- helpers ----------------
__device__ __forceinline__ void cpa16(const __half* dst_smem, const __half* src) {
    uint32_t d = (uint32_t)__cvta_generic_to_shared(dst_smem);
    asm volatile("cp.async.cg.shared.global [%0], [%1], 16;" :: "r"(d), "l"(src) : "memory");
}
#define CP_COMMIT() asm volatile("cp.async.commit_group;" ::: "memory")
#define CP_WAIT1()  asm volatile("cp.async.wait_group 1;" ::: "memory")
#define CP_WAIT2()  asm volatile("cp.async.wait_group 2;" ::: "memory")

// ====== dense fp16 wmma GEMM, tile 128x256, BK=64, 4-stage, B row-major ======
#define ALD   72
#define BLD   264
#define DASTG (128*ALD)
#define DBSTG (64*BLD)
#define DSTGB ((DASTG+DBSTG)*2)         /* 52224 bytes per stage */
#define DSMEM (4*DSTGB)                 /* 208896 bytes */

#define HG2_ISSUE(CH, ST, APTR, BPTR, KDIM, NDIM) do {                            \
    __half* As_ = (__half*)(sbuf + (ST)*DSTGB);                                   \
    __half* Bs_ = As_ + DASTG;                                                    \
    int k0_ = (CH) << 6;                                                          \
    _Pragma("unroll") for (int t_ = 0; t_ < 4; t_++) {                            \
        int idx_ = tid + t_*256; int row_ = idx_ >> 3, c_ = (idx_ & 7) * 8;       \
        cpa16(As_ + row_*ALD + c_, (APTR) + (size_t)(m0 + row_)*(KDIM) + k0_ + c_); } \
    _Pragma("unroll") for (int t_ = 0; t_ < 8; t_++) {                            \
        int idx_ = tid + t_*256; int row_ = idx_ >> 5, c_ = (idx_ & 31) * 8;      \
        cpa16(Bs_ + row_*BLD + c_, (BPTR) + (size_t)(k0_ + row_)*(NDIM) + n0 + c_); } \
} while (0)

#define HG2_COMP(ST) do {                                                         \
    const __half* As_ = (const __half*)(sbuf + (ST)*DSTGB);                       \
    const __half* Bs_ = As_ + DASTG;                                              \
    _Pragma("unroll") for (int kk = 0; kk < 4; kk++) {                            \
        wmma::fragment<wmma::matrix_a,16,16,16,__half,wmma::row_major> af[4];     \
        wmma::fragment<wmma::matrix_b,16,16,16,__half,wmma::row_major> bf[4];     \
        _Pragma("unroll") for (int i = 0; i < 4; i++)                             \
            wmma::load_matrix_sync(af[i], As_ + (wm*64 + i*16)*ALD + kk*16, ALD); \
        _Pragma("unroll") for (int j = 0; j < 4; j++)                             \
            wmma::load_matrix_sync(bf[j], Bs_ + (kk*16)*BLD + wn*64 + j*16, BLD); \
        _Pragma("unroll") for (int i = 0; i < 4; i++)                             \
            _Pragma("unroll") for (int j = 0; j < 4; j++)                         \
                wmma::mma_sync(acc[i][j], af[i], bf[j], acc[i][j]);               \
    }                                                                             \
} while (0)

// EPI 1: half out + bias + gelu   2: qkv half out (bias+rope+elu+mask)
template<int EPI>
__global__ void __launch_bounds__(256) hgemm2_k(
    const __half* __restrict__ A, const __half* __restrict__ Bm,
    const float* __restrict__ bias, void* __restrict__ Cv,
    int N, int K)
{
    extern __shared__ char sbuf[];
    int tid = threadIdx.x, wid = tid >> 5, lane = tid & 31;
    int wm = wid >> 2, wn = wid & 3;
    int m0 = blockIdx.y * 128, n0 = blockIdx.x * 256;
    int KT = K >> 6;

    wmma::fragment<wmma::accumulator,16,16,16,float> acc[4][4];
#pragma unroll
    for (int i = 0; i < 4; i++)
#pragma unroll
        for (int j = 0; j < 4; j++) wmma::fill_fragment(acc[i][j], 0.f);

    for (int s = 0; s < 3; s++) { if (s < KT) HG2_ISSUE(s, s, A, Bm, K, N); CP_COMMIT(); }
    for (int c = 0; c < KT; c++) {
        CP_WAIT2();
        __syncthreads();
        if (c + 3 < KT) HG2_ISSUE(c + 3, (c + 3) & 3, A, Bm, K, N);
        CP_COMMIT();
        HG2_COMP(c & 3);
    }
    __syncthreads();

    if (EPI == 2) {
        float* st = (float*)sbuf + wid * (16 * 68);
        int nb = n0 + wn * 64;
        int wtype = nb >> 9;          // 0=q 1=k 2=v
#pragma unroll
        for (int i = 0; i < 4; i++) {
#pragma unroll
            for (int j = 0; j < 4; j++)
                wmma::store_matrix_sync(st + j * 16, acc[i][j], 68, wmma::mem_row_major);
            __syncwarp();
#pragma unroll
            for (int e = 0; e < 32; e++) {
                int idx = e * 32 + lane;
                int r = idx >> 6, c = idx & 63;
                int m = m0 + wm*64 + i*16 + r;
                int n = nb + c;
                float val = st[r*68 + c] + bias[n];
                float outv;
                if (wtype < 2) {
                    int s = m % SS, b = m / SS;
                    if (b > BB - 1) b = BB - 1;
                    int jj = c & 31;
                    float cs = g_cs[(s*32 + jj)*2];
                    float sn = g_cs[(s*32 + jj)*2 + 1];
                    float partner = st[r*68 + (c ^ 32)] + bias[nb + (c ^ 32)];
                    float sgn = (c < 32) ? -1.f : 1.f;
                    float rot = val * cs + sgn * partner * sn;
                    float f = rot > 0.f ? rot + 1.f : expf(rot);
                    if (wtype == 1) f *= ((float)s < g_len[b]) ? 1.f : 0.f;
                    outv = f;
                } else {
                    outv = val;
                }
                g_qkvh[(size_t)m * NQKV + n] = __float2half_rn(outv);
            }
            __syncwarp();
        }
        return;
    }

    float* stg = (float*)sbuf + wid * 16 * 20;
#pragma unroll
    for (int i = 0; i < 4; i++)
#pragma unroll
        for (int j = 0; j < 4; j++) {
            wmma::store_matrix_sync(stg, acc[i][j], 20, wmma::mem_row_major);
            __syncwarp();
#pragma unroll
            for (int e = 0; e < 8; e++) {
                int idx = lane * 8 + e;
                int r = idx >> 4, cc = idx & 15;
                int m = m0 + wm*64 + i*16 + r;
                int n = n0 + wn*64 + j*16 + cc;
                float val = stg[r*20 + cc] + bias[n];
                val = 0.5f * val * (1.0f + erff(val * 0.70710678118654752f));
                ((__half*)Cv)[(size_t)m * N + n] = __float2half_rn(val);
            }
            __syncwarp();
        }
}

// ======= GEMM + residual + LayerNorm fused: tile 64x512, 512 thr, BK=32, 4-stage =======
#define LALD  40
#define LBLD  520
#define LASTG (64*LALD)
#define LBSTG (32*LBLD)
#define LSTGB ((LASTG+LBSTG)*2)         /* 38400 bytes */
#define LSMEM (4*LSTGB)                 /* 153600 bytes (>= 64*ELD*4 = 133120) */
#define ELD   520

#define LG_ISSUE(CH, ST, APTR, BPTR, KDIM) do {                                   \
    __half* As_ = (__half*)(sbuf + (ST)*LSTGB);                                   \
    __half* Bs_ = As_ + LASTG;                                                    \
    int k0_ = (CH) << 5;                                                          \
    if (tid < 256) { int row_ = tid >> 2, c_ = (tid & 3) * 8;                     \
        cpa16(As_ + row_*LALD + c_, (APTR) + (size_t)(m0 + row_)*(KDIM) + k0_ + c_); } \
    _Pragma("unroll") for (int t_ = 0; t_ < 4; t_++) {                            \
        int idx_ = tid + t_*512; int row_ = idx_ >> 6, c_ = (idx_ & 63) * 8;      \
        cpa16(Bs_ + row_*LBLD + c_, (BPTR) + (size_t)(k0_ + row_)*DD + c_); }     \
} while (0)

#define LG_COMP(ST) do {                                                          \
    const __half* As_ = (const __half*)(sbuf + (ST)*LSTGB);                       \
    const __half* Bs_ = As_ + LASTG;                                              \
    _Pragma("unroll") for (int kk = 0; kk < 2; kk++) {                            \
        wmma::fragment<wmma::matrix_a,16,16,16,__half,wmma::row_major> af[2];     \
        wmma::fragment<wmma::matrix_b,16,16,16,__half,wmma::row_major> bf[4];     \
        _Pragma("unroll") for (int i = 0; i < 2; i++)                             \
            wmma::load_matrix_sync(af[i], As_ + (wm*32 + i*16)*LALD + kk*16, LALD); \
        _Pragma("unroll") for (int j = 0; j < 4; j++)                             \
            wmma::load_matrix_sync(bf[j], Bs_ + (kk*16)*LBLD + wn*64 + j*16, LBLD); \
        _Pragma("unroll") for (int i = 0; i < 2; i++)                             \
            _Pragma("unroll") for (int j = 0; j < 4; j++)                         \
                wmma::mma_sync(acc[i][j], af[i], bf[j], acc[i][j]);               \
    }                                                                             \
} while (0)

__global__ void __launch_bounds__(512) gemm_ln_k(
    const __half* __restrict__ A, const __half* __restrict__ Bm,
    const float* __restrict__ bias, const float* __restrict__ ln_s,
    const float* __restrict__ ln_b, int K)
{
    extern __shared__ char sbuf[];
    __shared__ float rmean[64], rinv[64];
    int tid = threadIdx.x, wid = tid >> 5;
    int wm = wid >> 3, wn = wid & 7;    // 2 x 8
    int m0 = blockIdx.x * 64;
    int KT = K >> 5;

    wmma::fragment<wmma::accumulator,16,16,16,float> acc[2][4];
#pragma unroll
    for (int i = 0; i < 2; i++)
#pragma unroll
        for (int j = 0; j < 4; j++) wmma::fill_fragment(acc[i][j], 0.f);

    for (int s = 0; s < 3; s++) { if (s < KT) LG_ISSUE(s, s, A, Bm, K); CP_COMMIT(); }
    for (int c = 0; c < KT; c++) {
        CP_WAIT2();
        __syncthreads();
        if (c + 3 < KT) LG_ISSUE(c + 3, (c + 3) & 3, A, Bm, K);
        CP_COMMIT();
        LG_COMP(c & 3);
    }
    __syncthreads();

    float* ebuf = (float*)sbuf;
#pragma unroll
    for (int i = 0; i < 2; i++)
#pragma unroll
        for (int j = 0; j < 4; j++)
            wmma::store_matrix_sync(ebuf + (wm*32 + i*16)*ELD + wn*64 + j*16,
                                    acc[i][j], ELD, wmma::mem_row_major);
    __syncthreads();

    {
        int r = tid >> 3, sub = tid & 7;
        size_t mrow = (size_t)(m0 + r) * DD;
        float s = 0.f, ss = 0.f;
        for (int c = sub; c < DD; c += 8) {
            float v = ebuf[r*ELD + c] + bias[c] + g_x[mrow + c];
            ebuf[r*ELD + c] = v;
            s += v; ss += v * v;
        }
        s  += __shfl_down_sync(0xffffffffu, s, 4, 8);
        ss += __shfl_down_sync(0xffffffffu, ss, 4, 8);
        s  += __shfl_down_sync(0xffffffffu, s, 2, 8);
        ss += __shfl_down_sync(0xffffffffu, ss, 2, 8);
        s  += __shfl_down_sync(0xffffffffu, s, 1, 8);
        ss += __shfl_down_sync(0xffffffffu, ss, 1, 8);
        if (sub == 0) {
            float mean = s / (float)DD;
            float var = ss / (float)DD - mean * mean;
            rmean[r] = mean;
            rinv[r]  = rsqrtf(var + 1e-5f);
        }
    }
    __syncthreads();

#pragma unroll 4
    for (int it = 0; it < 64; it++) {
        int idx = it * 512 + tid;
        int rr = idx >> 9, c = idx & 511;
        float v = ebuf[rr*ELD + c];
        float o = (v - rmean[rr]) * rinv[rr] * ln_s[c] + ln_b[c];
        size_t oo = (size_t)(m0 + rr) * DD + c;
        g_x[oo]  = o;
        g_xh[oo] = __float2half_rn(o);
    }
}

// ------ conv-embedding GEMM (gathered A, B col-major [N][K]), 3-stage ------
#define CASTG (128*ALD)
#define CBSTG (256*ALD)
#define CSTGB ((CASTG+CBSTG)*2)         /* 55296 */
#define CSMEM (3*CSTGB)                 /* 165888 */

__global__ void __launch_bounds__(256) conv_hgemm2_k(
    const int* __restrict__ tok, const float* __restrict__ conv_b,
    const float* __restrict__ pos)
{
    extern __shared__ char sbuf[];
    __shared__ int toks[16][128];
    int tid = threadIdx.x, wid = tid >> 5, lane = tid & 31;
    int wm = wid >> 2, wn = wid & 3;
    int m0 = blockIdx.y * 128, n0 = blockIdx.x * 256;
    const int KT = KCONV >> 6;   // 128

    if (tid < 128) {
        int r = m0 + tid;
        int b = r >> 8, nn = r & 255;
        int base = b * LL + nn * PP;
#pragma unroll
        for (int p = 0; p < 16; p++) toks[p][tid] = tok[base + p];
    }
    __syncthreads();

    wmma::fragment<wmma::accumulator,16,16,16,float> acc[4][4];
#pragma unroll
    for (int i = 0; i < 4; i++)
#pragma unroll
        for (int j = 0; j < 4; j++) wmma::fill_fragment(acc[i][j], 0.f);

#define CV2_ISSUE(CH, ST) do {                                                    \
    __half* As_ = (__half*)(sbuf + (ST)*CSTGB);                                   \
    __half* Bs_ = As_ + CASTG;                                                    \
    int k0_ = (CH) << 6; int p_ = k0_ >> 9, i0_ = k0_ & 511;                      \
    _Pragma("unroll") for (int t_ = 0; t_ < 4; t_++) {                            \
        int idx_ = tid + t_*256; int row_ = idx_ >> 3, c_ = (idx_ & 7) * 8;       \
        int tk_ = toks[p_][row_];                                                 \
        cpa16(As_ + row_*ALD + c_, g_embt + (size_t)tk_*DD + i0_ + c_); }         \
    _Pragma("unroll") for (int t_ = 0; t_ < 8; t_++) {                            \
        int idx_ = tid + t_*256; int row_ = idx_ >> 3, c_ = (idx_ & 7) * 8;       \
        cpa16(Bs_ + row_*ALD + c_, g_Wc + (size_t)(n0 + row_)*KCONV + k0_ + c_); } \
} while (0)

#define CVC_COMP(ST) do {                                                         \
    const __half* As_ = (const __half*)(sbuf + (ST)*CSTGB);                       \
    const __half* Bs_ = As_ + CASTG;                                              \
    _Pragma("unroll") for (int kk = 0; kk < 4; kk++) {                            \
        wmma::fragment<wmma::matrix_a,16,16,16,__half,wmma::row_major> af[4];     \
        wmma::fragment<wmma::matrix_b,16,16,16,__half,wmma::col_major> bf[4];     \
        _Pragma("unroll") for (int i = 0; i < 4; i++)                             \
            wmma::load_matrix_sync(af[i], As_ + (wm*64 + i*16)*ALD + kk*16, ALD); \
        _Pragma("unroll") for (int j = 0; j < 4; j++)                             \
            wmma::load_matrix_sync(bf[j], Bs_ + (wn*64 + j*16)*ALD + kk*16, ALD); \
        _Pragma("unroll") for (int i = 0; i < 4; i++)                             \
            _Pragma("unroll") for (int j = 0; j < 4; j++)                         \
                wmma::mma_sync(acc[i][j], af[i], bf[j], acc[i][j]);               \
    }                                                                             \
} while (0)

    for (int s = 0; s < 2; s++) { CV2_ISSUE(s, s); CP_COMMIT(); }
    for (int c = 0; c < KT; c++) {
        CP_WAIT1();
        __syncthreads();
        if (c + 2 < KT) CV2_ISSUE(c + 2, (c + 2) % 3);
        CP_COMMIT();
        CVC_COMP(c % 3);
    }
    __syncthreads();

    float* stg = (float*)sbuf + wid * 16 * 20;
#pragma unroll
    for (int i = 0; i < 4; i++)
#pragma unroll
        for (int j = 0; j < 4; j++) {
            wmma::store_matrix_sync(stg, acc[i][j], 20, wmma::mem_row_major);
            __syncwarp();
#pragma unroll
            for (int e = 0; e < 8; e++) {
                int idx = lane * 8 + e;
                int r = idx >> 4, cc = idx & 15;
                int mrow = m0 + wm*64 + i*16 + r;
                int b = mrow >> 8, nn = mrow & 255;
                int s = nn + 1;
                int n = n0 + wn*64 + j*16 + cc;
                float val = stg[r*20 + cc] + conv_b[n] + pos[(size_t)s*DD + n];
                size_t o = ((size_t)(b*SS + s))*DD + n;
                g_x[o]  = val;
                g_xh[o] = __float2half_rn(val);
            }
            __syncwarp();
        }
}

// ---------------- prologue pack kernels ----------------
__global__ void half4_k(const float4* __restrict__ src, __half* __restrict__ dst, int n4) {
    int i = blockIdx.x * 256 + threadIdx.x;
    if (i >= n4) return;
    float4 v = src[i];
    __half2 a = __floats2half2_rn(v.x, v.y);
    __half2 b = __floats2half2_rn(v.z, v.w);
    __half2* d = (__half2*)(dst + (size_t)i * 4);
    d[0] = a; d[1] = b;
}

__global__ void pack_qkvc_k(const float* __restrict__ Wq, const float* __restrict__ Wk,
                            const float* __restrict__ Wv) {
    size_t idx = (size_t)blockIdx.x * 256 + threadIdx.x;
    if (idx >= (size_t)NLAY * DD * NQKV) return;
    int l = (int)(idx / (DD * NQKV));
    int rem = (int)(idx % (DD * NQKV));
    int k = rem / NQKV, n = rem % NQKV;
    int w = n >> 9, nn = n & 511;
    const float* W = (w == 0) ? Wq : (w == 1) ? Wk : Wv;
    g_Wqkv[idx] = __float2half_rn(W[((size_t)l * DD + k) * DD + nn]);
}

__global__ void pack_qkvb_k(const float* __restrict__ bq, const float* __restrict__ bk,
                            const float* __restrict__ bv) {
    int idx = blockIdx.x * 256 + threadIdx.x;
    if (idx >= NLAY * NQKV) return;
    int i = idx / NQKV, n = idx % NQKV;
    int w = n >> 9, nn = n & 511;
    const float* Bv = (w == 0) ? bq : (w == 1) ? bk : bv;
    g_bqkv[idx] = Bv[i * DD + nn];
}

__global__ void __launch_bounds__(256) pack_convw2_k(const float* __restrict__ cw) {
    __shared__ float row[KCONV];
    int o = blockIdx.x;
    int tid = threadIdx.x;
    for (int i = tid; i < KCONV; i += 256) row[i] = cw[(size_t)o * KCONV + i];
    __syncthreads();
    for (int k = tid; k < KCONV; k += 256) {
        int i = k & 511, p = k >> 9;
        g_Wc[(size_t)o * KCONV + k] = __float2half_rn(row[i * PP + p]);
    }
}

__global__ void rope_tab_k() {
    int idx = blockIdx.x * 256 + threadIdx.x;
    if (idx >= SS * 32) return;
    int s = idx >> 5, j = idx & 31;
    float ang = (float)s * exp2f(-(float)j * (13.287712379549449f / 32.f));
    g_cs[idx * 2]     = cosf(ang);
    g_cs[idx * 2 + 1] = sinf(ang);
}

// ---------------- small kernels ----------------
__global__ void lengths_k(const float* __restrict__ mask) {
    __shared__ float sh[256];
    int b = blockIdx.x;
    float s = 0.f;
    for (int i = threadIdx.x; i < LL; i += 256) s += mask[(size_t)b * LL + i];
    sh[threadIdx.x] = s;
    __syncthreads();
    for (int st = 128; st > 0; st >>= 1) {
        if (threadIdx.x < st) sh[threadIdx.x] += sh[threadIdx.x + st];
        __syncthreads();
    }
    if (threadIdx.x == 0) g_len[b] = ceilf((sh[0] + 1.0f) / (float)PP);
}

__global__ void init_cls_k(const float* __restrict__ cls, const float* __restrict__ pos) {
    int idx = blockIdx.x * blockDim.x + threadIdx.x;
    if (idx >= BB * DD) return;
    int b = idx >> 9, d = idx & 511;
    float v = cls[d] + pos[d];
    size_t o = (size_t)b * SS * DD + d;
    g_x[o] = v; g_xh[o] = __float2half_rn(v);
}

__global__ void zero_pad_k() {
    int i = blockIdx.x * blockDim.x + threadIdx.x;
    int n = (TPAD - TT) * DD;
    if (i < n) {
        g_x[(size_t)TT * DD + i] = 0.f;
        g_xh[(size_t)TT * DD + i] = __float2half_rn(0.f);
        g_attn[(size_t)TT * DD + i] = __float2half_rn(0.f);
    }
}

// kv partial: part p covers s in [p*SPART, min(SS, (p+1)*SPART))
__global__ void __launch_bounds__(256) kv3_k() {
    int bh = blockIdx.x, part = blockIdx.y;
    int b = bh >> 3, h = bh & 7;
    int sbeg = part * SPART;
    int send = min(SS, sbeg + SPART);
    __shared__ float kf_sh[8][64], v_sh[8][64];
    int tid = threadIdx.x;
    int m = tid & 63, dg = tid >> 6;
    float acc[16];
#pragma unroll
    for (int jj = 0; jj < 16; jj++) acc[jj] = 0.f;
    float ksum = 0.f;
    for (int s0 = sbeg; s0 < send; s0 += 8) {
        __syncthreads();
#pragma unroll
        for (int u = 0; u < 4; u++) {
            int idx = tid + u * 256;
            int which = idx >> 9;
            int rr = (idx >> 6) & 7;
            int cc = idx & 63;
            int s = s0 + rr;
            float val = (s < send)
                ? __half2float(g_qkvh[(size_t)(b*SS + s)*NQKV + (which ? 1024 : 512) + h*64 + cc])
                : 0.f;
            if (which) v_sh[rr][cc] = val; else kf_sh[rr][cc] = val;
        }
        __syncthreads();
#pragma unroll
        for (int r = 0; r < 8; r++) {
            float vr = v_sh[r][m];
#pragma unroll
            for (int jj = 0; jj < 16; jj++) acc[jj] += kf_sh[r][dg*16 + jj] * vr;
        }
        if (tid < 64) {
#pragma unroll
            for (int r = 0; r < 8; r++) ksum += kf_sh[r][tid];
        }
    }
#pragma unroll
    for (int jj = 0; jj < 16; jj++)
        g_kvp[part][((size_t)bh * DHD + dg*16 + jj) * DHD + m] = acc[jj];
    if (tid < 64) g_ksump[part][bh * DHD + tid] = ksum;
}

// attn chunk: block (bh, ch) handles tokens [ch*32, min(SS, ch*32+32))
__global__ void __launch_bounds__(256) attn3_k() {
    int bh = blockIdx.x, ch = blockIdx.y;
    int b = bh >> 3, h = bh & 7;
    int sbeg = ch * 32;
    int send = min(SS, sbeg + 32);
    __shared__ float kvs[DHD * DHD];
    __shared__ float ks[DHD];
    __shared__ float q4[4][64];
    __shared__ float red[4][64];
    __shared__ float part[4][4][64];
    __shared__ float zsh[4];
    int tid = threadIdx.x, wid = tid >> 5, lane = tid & 31;
    int m = tid & 63, dg = tid >> 6;
    for (int i = tid; i < DHD * DHD; i += 256) {
        size_t o = (size_t)bh * DHD * DHD + i;
        kvs[i] = g_kvp[0][o] + g_kvp[1][o] + g_kvp[2][o] + g_kvp[3][o];
    }
    if (tid < 64) {
        int o = bh * DHD + tid;
        ks[tid] = g_ksump[0][o] + g_ksump[1][o] + g_ksump[2][o] + g_ksump[3][o];
    }
    __syncthreads();
    for (int s0 = sbeg; s0 < send; s0 += 4) {
        int r = tid >> 6, c = tid & 63;
        int sr = s0 + r;
        q4[r][c] = (sr < send)
            ? __half2float(g_qkvh[(size_t)(b*SS + sr)*NQKV + h*64 + c]) : 0.f;
        __syncthreads();
        red[r][c] = q4[r][c] * ks[c];
        __syncthreads();
        if (wid < 4) {
            float v = red[wid][lane] + red[wid][lane + 32];
            for (int o = 16; o; o >>= 1) v += __shfl_down_sync(0xffffffffu, v, o);
            if (lane == 0) zsh[wid] = 1.f / (v + 1e-6f);
        }
        float a[4] = {0.f, 0.f, 0.f, 0.f};
#pragma unroll
        for (int jj = 0; jj < 16; jj++) {
            int d = dg*16 + jj;
            float kc = kvs[d * DHD + m];
#pragma unroll
            for (int rr = 0; rr < 4; rr++) a[rr] += q4[rr][d] * kc;
        }
#pragma unroll
        for (int rr = 0; rr < 4; rr++) part[dg][rr][m] = a[rr];
        __syncthreads();
        {
            int rr = tid >> 6, mm = tid & 63;
            int s = s0 + rr;
            if (s < send) {
                float o = (part[0][rr][mm] + part[1][rr][mm] +
                           part[2][rr][mm] + part[3][rr][mm]) * zsh[rr];
                g_attn[((size_t)(b*SS + s))*DD + h*64 + mm] = __float2half_rn(o);
            }
        }
        __syncthreads();
    }
}

// final LN on token 0 + classifier head
__global__ void __launch_bounds__(256) final_k(
    const float* __restrict__ lnf_s, const float* __restrict__ lnf_b,
    const float* __restrict__ ow, const float* __restrict__ ob,
    float* __restrict__ out)
{
    int b = blockIdx.x, tid = threadIdx.x;
    size_t base = (size_t)b * SS * DD;
    float v0 = g_x[base + tid];
    float v1 = g_x[base + tid + 256];
    float s = v0 + v1, ss = v0 * v0 + v1 * v1;
    __shared__ float rs[8], rss[8];
    __shared__ float row[DD];
    for (int o = 16; o; o >>= 1) {
        s  += __shfl_down_sync(0xffffffffu, s, o);
        ss += __shfl_down_sync(0xffffffffu, ss, o);
    }
    int w = tid >> 5;
    if ((tid & 31) == 0) { rs[w] = s; rss[w] = ss; }
    __syncthreads();
    if (tid == 0) {
        float S1 = 0.f, S2 = 0.f;
        for (int i = 0; i < 8; i++) { S1 += rs[i]; S2 += rss[i]; }
        rs[0] = S1 / (float)DD;
        rss[0] = S2 / (float)DD;
    }
    __syncthreads();
    float mean = rs[0];
    float inv = rsqrtf(rss[0] - mean * mean + 1e-5f);
    row[tid]       = (v0 - mean) * inv * lnf_s[tid] + lnf_b[tid];
    row[tid + 256] = (v1 - mean) * inv * lnf_s[tid + 256] + lnf_b[tid + 256];
    __syncthreads();
    for (int c = 0; c < NCLS; c++) {
        float p = row[tid] * ow[tid * NCLS + c] + row[tid + 256] * ow[(tid + 256) * NCLS + c];
        for (int o = 16; o; o >>= 1) p += __shfl_down_sync(0xffffffffu, p, o);
        if ((tid & 31) == 0) rs[tid >> 5] = p;
        __syncthreads();
        if (tid == 0) {
            float t2 = 0.f;
            for (int i = 0; i < 8; i++) t2 += rs[i];
            out[b * NCLS + c] = t2 + ob[c];
        }
        __syncthreads();
    }
}

// ---------------- host driver ----------------
extern "C" void kernel_launch(void* const* d_in, const int* in_sizes, int n_in,
                              void* d_out, int out_size)
{
    const int*   inputs     = (const int*)  d_in[0];
    const float* input_mask = (const float*)d_in[1];
    const float* emb        = (const float*)d_in[2];
    const float* conv_w     = (const float*)d_in[3];
    const float* conv_b     = (const float*)d_in[4];
    const float* pos        = (const float*)d_in[5];
    const float* cls        = (const float*)d_in[6];
    const float* Wq         = (const float*)d_in[7];
    const float* bq         = (const float*)d_in[8];
    const float* Wk         = (const float*)d_in[9];
    const float* bk         = (const float*)d_in[10];
    const float* Wv         = (const float*)d_in[11];
    const float* bv         = (const float*)d_in[12];
    const float* Wo         = (const float*)d_in[13];
    const float* bo         = (const float*)d_in[14];
    const float* ln1_s      = (const float*)d_in[15];
    const float* ln1_b      = (const float*)d_in[16];
    const float* ln2_s      = (const float*)d_in[17];
    const float* ln2_b      = (const float*)d_in[18];
    const float* W1         = (const float*)d_in[19];
    const float* b1         = (const float*)d_in[20];
    const float* W2         = (const float*)d_in[21];
    const float* b2         = (const float*)d_in[22];
    const float* lnf_s      = (const float*)d_in[23];
    const float* lnf_b      = (const float*)d_in[24];
    const float* out_w      = (const float*)d_in[25];
    const float* out_b      = (const float*)d_in[26];
    float* out = (float*)d_out;

    float  *pbqkv;
    __half *pxh, *pattn, *ph, *pWqkv, *pWoh, *pW1h, *pW2h, *pembt;
    cudaGetSymbolAddress((void**)&pxh,   g_xh);
    cudaGetSymbolAddress((void**)&pattn, g_attn);
    cudaGetSymbolAddress((void**)&ph,    g_h);
    cudaGetSymbolAddress((void**)&pWqkv, g_Wqkv);
    cudaGetSymbolAddress((void**)&pbqkv, g_bqkv);
    cudaGetSymbolAddress((void**)&pWoh,  g_Woh);
    cudaGetSymbolAddress((void**)&pW1h,  g_W1h);
    cudaGetSymbolAddress((void**)&pW2h,  g_W2h);
    cudaGetSymbolAddress((void**)&pembt, g_embt);

    cudaFuncSetAttribute(hgemm2_k<1>,   cudaFuncAttributeMaxDynamicSharedMemorySize, DSMEM);
    cudaFuncSetAttribute(hgemm2_k<2>,   cudaFuncAttributeMaxDynamicSharedMemorySize, DSMEM);
    cudaFuncSetAttribute(conv_hgemm2_k, cudaFuncAttributeMaxDynamicSharedMemorySize, CSMEM);
    cudaFuncSetAttribute(gemm_ln_k,     cudaFuncAttributeMaxDynamicSharedMemorySize, LSMEM);

    // fork a side stream for the layer-weight converts (graph-captured fork/join)
    cudaStream_t s2;
    cudaStreamCreateWithFlags(&s2, cudaStreamNonBlocking);
    cudaEvent_t evFork, evJoin;
    cudaEventCreateWithFlags(&evFork, cudaEventDisableTiming);
    cudaEventCreateWithFlags(&evJoin, cudaEventDisableTiming);

    cudaEventRecord(evFork, 0);
    cudaStreamWaitEvent(s2, evFork, 0);

    // main stream: conv path
    pack_convw2_k<<<DD, 256>>>(conv_w);
    half4_k<<<(32000 * DD / 4 + 255) / 256, 256>>>((const float4*)emb, pembt, 32000 * DD / 4);
    init_cls_k<<<(BB * DD + 255) / 256, 256>>>(cls, pos);
    conv_hgemm2_k<<<dim3(DD / 256, MCONV / 128), 256, CSMEM>>>(inputs, conv_b, pos);

    // side stream: layer-weight converts + setup
    pack_qkvc_k<<<(int)(((size_t)NLAY * DD * NQKV + 255) / 256), 256, 0, s2>>>(Wq, Wk, Wv);
    pack_qkvb_k<<<(NLAY * NQKV + 255) / 256, 256, 0, s2>>>(bq, bk, bv);
    half4_k<<<(NLAY * DD * DD / 4 + 255) / 256, 256, 0, s2>>>((const float4*)Wo, pWoh, NLAY * DD * DD / 4);
    half4_k<<<(NLAY * DD * FFD / 4 + 255) / 256, 256, 0, s2>>>((const float4*)W1, pW1h, NLAY * DD * FFD / 4);
    half4_k<<<(NLAY * FFD * DD / 4 + 255) / 256, 256, 0, s2>>>((const float4*)W2, pW2h, NLAY * FFD * DD / 4);
    rope_tab_k<<<(SS * 32 + 255) / 256, 256, 0, s2>>>();
    lengths_k<<<BB, 256, 0, s2>>>(input_mask);
    zero_pad_k<<<((TPAD - TT) * DD + 255) / 256, 256, 0, s2>>>();

    cudaEventRecord(evJoin, s2);
    cudaStreamWaitEvent(0, evJoin, 0);

    dim3 gQKV(NQKV / 256, TPAD / 128);  // (6, 65)
    dim3 gF(FFD / 256, TPAD / 128);     // (8, 65)
    int gLN = TPAD / 64;                // 130

    for (int i = 0; i < NLAY; i++) {
        hgemm2_k<2><<<gQKV, 256, DSMEM>>>(pxh, pWqkv + (size_t)i*DD*NQKV,
                                          pbqkv + (size_t)i*NQKV, nullptr, NQKV, DD);
        kv3_k<<<dim3(BB * HH, KVPARTS), 256>>>();
        attn3_k<<<dim3(BB * HH, 9), 256>>>();
        gemm_ln_k<<<gLN, 512, LSMEM>>>(pattn, pWoh + (size_t)i*DD*DD,
                                       bo + (size_t)i*DD,
                                       ln1_s + (size_t)i*DD, ln1_b + (size_t)i*DD, DD);
        hgemm2_k<1><<<gF, 256, DSMEM>>>(pxh, pW1h + (size_t)i*DD*FFD,
                                        b1 + (size_t)i*FFD, ph, FFD, DD);
        gemm_ln_k<<<gLN, 512, LSMEM>>>(ph, pW2h + (size_t)i*FFD*DD,
                                       b2 + (size_t)i*DD,
                                       ln2_s + (size_t)i*DD, ln2_b + (size_t)i*DD, FFD);
    }

    final_k<<<BB, 256>>>(lnf_s, lnf_b, out_w, out_b, out);
}